// round 12
// baseline (speedup 1.0000x reference)
#include <cuda_runtime.h>
#include <math.h>

#define Bn   32
#define Cn   256
#define Hn   64
#define Wn   64
#define HWn  4096
#define AUXn 64
#define RANKn 64
#define HIDn 256
#define OSn  8
#define PI_F 3.14159265358979323846f

// ---------------- scratch ----------------
__device__ __align__(128) float d_gpart[Bn * 16 * Cn];
__device__ __align__(128) float d_av0[Bn * HWn];
__device__ __align__(128) float d_av1[Bn * HWn];
__device__ __align__(128) float d_mx0[Bn * HWn];
__device__ __align__(128) float d_mx1[Bn * HWn];
__device__ __align__(128) float d_h[Bn * HIDn];
__device__ __align__(128) float d_phic[Bn * RANKn];
__device__ __align__(128) float d_phis[Bn * RANKn];
__device__ __align__(128) float d_Ep[Bn * 33 * Cn];
__device__ __align__(128) float d_Mp[Bn * 8 * Cn];
__device__ __align__(128) float d_Sp[Bn * 9 * OSn];
__device__ __align__(128) float d_MBp[Bn * 8 * OSn];

// dependency counters (reset by the final F block each run)
__device__ int g_cK[Bn];
__device__ int g_cA[Bn];
__device__ int g_cB;
__device__ int g_cC;
__device__ int g_cF;

// block-count constants
#define NB_K1 1024
#define NB_A  256
#define NB_B  32
#define NB_C  1329     // 1024 gemm + 256 Mp + 32 bias + 17 small
#define NB_F  1024
#define B0_A  (NB_K1)
#define B0_B  (B0_A + NB_A)
#define B0_C  (B0_B + NB_B)
#define B0_F  (B0_C + NB_C)
#define NB_TOT (B0_F + NB_F)

struct SK1 { float rs[128 * 33]; float avp[8][256]; float mxp[8][256]; };
struct SC  { float Wt[8 * 512]; float h[32 * 33]; float phi[32 * 68]; };
struct SA  { float in[Cn + AUXn]; float red[8 * 32]; };
struct SB  { float h[HIDn]; float pcred[8 * 32]; float psred[8 * 32]; };
union SMu {
    SK1 k1;
    SC  c;
    SA  a;
    SB  b2;
    float4 xbuf[8 * 256];   // 32 KB F-stage x prefetch
};

__device__ __forceinline__ void spin_ge(int* ctr, int target) {
    if (threadIdx.x == 0) {
        while (atomicAdd(ctr, 0) < target) __nanosleep(64);
    }
    __syncthreads();
}

__global__ void __launch_bounds__(256) mega(
        const float* __restrict__ x, float* __restrict__ out,
        const float* __restrict__ a,
        const float* __restrict__ W_pre, const float* __restrict__ b_pre,
        const float* __restrict__ W_pc,  const float* __restrict__ b_pc,
        const float* __restrict__ W_ps,  const float* __restrict__ b_ps,
        const float* __restrict__ W_Wc,  const float* __restrict__ b_Wc,
        const float* __restrict__ W_bc,  const float* __restrict__ b_bc,
        const float* __restrict__ W_Ws,  const float* __restrict__ b_Ws,
        const float* __restrict__ W_bs,  const float* __restrict__ b_bs) {
    const int blk = blockIdx.x;
    const int t   = threadIdx.x;
    const int lane = t & 31;
    const int warp = t >> 5;

    __shared__ SMu sm;
    __shared__ float sig_s[32];
    __shared__ float sms_s[OSn];
    __shared__ float pc_s[10];

    if (blk < NB_K1) {
        // ================= stage K1: stats over x (b-major order) =================
        const int b     = blk >> 5;
        const int rem   = blk & 31;
        const int tile  = rem >> 1;
        const int chalf = rem & 1;
        const int pos0  = tile * 256;

        const float4* xb = (const float4*)(x + (size_t)b * Cn * HWn);
        const int p4base = (pos0 >> 2) + lane;

        float4 av0 = {0,0,0,0}, av1 = {0,0,0,0};
        const float NI = -3.402823466e38f;
        float4 mx0 = {NI,NI,NI,NI}, mx1 = mx0;

        const int lcbase = warp * 16;
        const int cbase  = chalf * 128 + lcbase;
        #pragma unroll 4
        for (int cc = 0; cc < 16; cc++) {
            const size_t row = (size_t)(cbase + cc) * (HWn / 4) + p4base;
            float4 v0 = __ldg(&xb[row]);
            float4 v1 = __ldg(&xb[row + 32]);

            av0.x += v0.x; av0.y += v0.y; av0.z += v0.z; av0.w += v0.w;
            av1.x += v1.x; av1.y += v1.y; av1.z += v1.z; av1.w += v1.w;
            mx0.x = fmaxf(mx0.x, v0.x); mx0.y = fmaxf(mx0.y, v0.y); mx0.z = fmaxf(mx0.z, v0.z); mx0.w = fmaxf(mx0.w, v0.w);
            mx1.x = fmaxf(mx1.x, v1.x); mx1.y = fmaxf(mx1.y, v1.y); mx1.z = fmaxf(mx1.z, v1.z); mx1.w = fmaxf(mx1.w, v1.w);

            float r = ((v0.x + v0.y) + (v0.z + v0.w)) + ((v1.x + v1.y) + (v1.z + v1.w));
            sm.k1.rs[(lcbase + cc) * 33 + lane] = r;
        }

        *(float4*)&sm.k1.avp[warp][lane * 4]       = av0;
        *(float4*)&sm.k1.avp[warp][128 + lane * 4] = av1;
        *(float4*)&sm.k1.mxp[warp][lane * 4]       = mx0;
        *(float4*)&sm.k1.mxp[warp][128 + lane * 4] = mx1;
        __syncthreads();

        {
            float s = 0.f, m = NI;
            #pragma unroll
            for (int w = 0; w < 8; w++) { s += sm.k1.avp[w][t]; m = fmaxf(m, sm.k1.mxp[w][t]); }
            float* avh = chalf ? d_av1 : d_av0;
            float* mxh = chalf ? d_mx1 : d_mx0;
            avh[b * HWn + pos0 + t] = s;
            mxh[b * HWn + pos0 + t] = m;
        }
        if (t < 128) {
            float g = 0.f;
            #pragma unroll
            for (int l = 0; l < 32; l++) g += sm.k1.rs[t * 33 + l];
            d_gpart[(b * 16 + tile) * Cn + chalf * 128 + t] = g;
        }
        __threadfence();
        __syncthreads();
        if (t == 0) atomicAdd(&g_cK[b], 1);
    } else if (blk < B0_B) {
        // ================= stage A: partial h (per-batch gate) =================
        const int q = blk - B0_A;
        const int b = q >> 3, part = q & 7;
        spin_ge(&g_cK[b], 32);

        {
            float g = 0.f;
            #pragma unroll
            for (int tl = 0; tl < 16; tl++) g += d_gpart[(b * 16 + tl) * Cn + t];
            sm.a.in[t] = g * (1.f / (float)HWn);
            if (t < AUXn) sm.a.in[Cn + t] = __ldg(a + b * AUXn + t);
        }
        __syncthreads();

        const int j  = t & 31;
        const int ks = t >> 5;
        const int jg = part * 32 + j;
        float acc = (ks == 0) ? __ldg(b_pre + jg) : 0.f;
        const int i0 = ks * 40;
        #pragma unroll
        for (int k = 0; k < 40; k++)
            acc = fmaf(sm.a.in[i0 + k], __ldg(W_pre + (i0 + k) * HIDn + jg), acc);
        sm.a.red[ks * 32 + j] = acc;
        __syncthreads();

        if (t < 32) {
            float s = 0.f;
            #pragma unroll
            for (int kk = 0; kk < 8; kk++) s += sm.a.red[kk * 32 + t];
            d_h[b * HIDn + part * 32 + t] = fmaxf(s, 0.f);
        }
        __threadfence();
        __syncthreads();
        if (t == 0) atomicAdd(&g_cA[b], 1);
    } else if (blk < B0_C) {
        // ================= stage B: phi (per-batch gate) =================
        const int b = blk - B0_B;
        spin_ge(&g_cA[b], 8);

        sm.b2.h[t] = d_h[b * HIDn + t];
        __syncthreads();

        const int j  = t & 31;
        const int ks = t >> 5;
        {
            float pc = (ks == 0) ? __ldg(b_pc + j) : 0.f;
            float ps = (ks == 0) ? __ldg(b_ps + j) : 0.f;
            const int k0 = ks * 32;
            #pragma unroll 4
            for (int k = 0; k < 32; k++) {
                float hk = sm.b2.h[k0 + k];
                pc = fmaf(hk, __ldg(W_pc + (k0 + k) * RANKn + j), pc);
                ps = fmaf(hk, __ldg(W_ps + (k0 + k) * RANKn + j), ps);
            }
            sm.b2.pcred[ks * 32 + j] = pc;
            sm.b2.psred[ks * 32 + j] = ps;
        }
        __syncthreads();

        if (t < 32) {
            float p = 0.f;
            #pragma unroll
            for (int kk = 0; kk < 8; kk++) p += sm.b2.pcred[kk * 32 + t];
            float w = 1.f + (PI_F - 1.f) * (float)t / 31.f;
            float u = p * w;
            d_phic[b * RANKn + t]      = sinf(u);
            d_phic[b * RANKn + t + 32] = cosf(u);
        } else if (t < 64) {
            int r = t - 32;
            float p = 0.f;
            #pragma unroll
            for (int kk = 0; kk < 8; kk++) p += sm.b2.psred[kk * 32 + r];
            float w = 1.f + (PI_F - 1.f) * (float)r / 31.f;
            float u = p * w;
            d_phis[b * RANKn + r]      = sinf(u);
            d_phis[b * RANKn + r + 32] = cosf(u);
        }
        __threadfence();
        __syncthreads();
        if (t == 0) atomicAdd(&g_cB, 1);
    } else if (blk < B0_F) {
        // ================= stage C: contractions =================
        const int blk0 = blk - B0_C;

        if (blk0 < 1024) {
            // ---- GEMM: kt covers 8 k's, ct covers 8 c's; W prefetched BEFORE spin ----
            const int kt = blk0 >> 5;
            const int ct = blk0 & 31;

            const float4* Wg = (const float4*)(W_Wc + (size_t)(kt * 8) * (Cn * RANKn) + ct * 512);
            #pragma unroll
            for (int i = t; i < 1024; i += 256) {
                int kk = i >> 7, jj = i & 127;
                ((float4*)sm.c.Wt)[i] = __ldg(&Wg[(size_t)kk * 4096 + jj]);
            }

            spin_ge(&g_cB, 32);

            {
                int bb = t >> 3, kk = t & 7;
                sm.c.h[bb * 33 + kk] = d_h[bb * HIDn + kt * 8 + kk];
            }
            for (int i = t; i < 2048; i += 256) {
                int bb = i >> 6, r = i & 63;
                sm.c.phi[bb * 68 + r] = d_phic[bb * RANKn + r];
            }
            __syncthreads();

            float4 ph[16];
            #pragma unroll
            for (int i = 0; i < 16; i++) ph[i] = *(const float4*)(sm.c.phi + lane * 68 + i * 4);

            const int c8 = warp;    // 8 warps -> 8 channels
            float acc = 0.f;
            #pragma unroll
            for (int kk = 0; kk < 8; kk++) {
                const float4* w4 = (const float4*)(sm.c.Wt + kk * 512 + c8 * 64);
                float d0 = 0.f, d1 = 0.f;
                #pragma unroll
                for (int q = 0; q < 16; q += 2) {
                    float4 wa = w4[q], wb = w4[q + 1];
                    d0 = fmaf(wa.x, ph[q].x, d0);
                    d0 = fmaf(wa.y, ph[q].y, d0);
                    d0 = fmaf(wa.z, ph[q].z, d0);
                    d0 = fmaf(wa.w, ph[q].w, d0);
                    d1 = fmaf(wb.x, ph[q + 1].x, d1);
                    d1 = fmaf(wb.y, ph[q + 1].y, d1);
                    d1 = fmaf(wb.z, ph[q + 1].z, d1);
                    d1 = fmaf(wb.w, ph[q + 1].w, d1);
                }
                acc = fmaf(sm.c.h[lane * 33 + kk], d0 + d1, acc);
            }
            d_Ep[(lane * 33 + kt) * Cn + ct * 8 + c8] = acc;
        } else if (blk0 < 1280) {
            const int q = blk0 - 1024;
            const int ct8 = q & 31, kc = q >> 5;
            const int c = ct8 * 8 + warp;
            spin_ge(&g_cB, 32);
            for (int i = t; i < 32 * 32; i += 256) {
                int bb = i >> 5, kk = i & 31;
                sm.c.h[bb * 33 + kk] = d_h[bb * HIDn + kc * 32 + kk];
            }
            __syncthreads();
            float a0 = 0.f, a1 = 0.f;
            const float* Wb = W_bc + (size_t)(kc * 32) * Cn + c;
            #pragma unroll 4
            for (int kk = 0; kk < 32; kk += 2) {
                a0 = fmaf(sm.c.h[lane * 33 + kk],     __ldg(Wb + (size_t)kk * Cn), a0);
                a1 = fmaf(sm.c.h[lane * 33 + kk + 1], __ldg(Wb + (size_t)(kk + 1) * Cn), a1);
            }
            d_Mp[(lane * 8 + kc) * Cn + c] = a0 + a1;
        } else if (blk0 < 1312) {
            const int ct8 = blk0 - 1280;
            const int c = ct8 * 8 + warp;
            spin_ge(&g_cB, 32);
            for (int i = t; i < 32 * 64; i += 256) {
                int bb = i >> 6, r = i & 63;
                sm.c.phi[bb * 68 + r] = d_phic[bb * RANKn + r];
            }
            __syncthreads();
            float acc = 0.f;
            const float4* bw4 = (const float4*)(b_Wc + c * RANKn);
            #pragma unroll
            for (int r4 = 0; r4 < 16; r4++) {
                float4 w = __ldg(&bw4[r4]);
                float4 p = *(const float4*)(sm.c.phi + lane * 68 + r4 * 4);
                acc = fmaf(w.x, p.x, acc);
                acc = fmaf(w.y, p.y, acc);
                acc = fmaf(w.z, p.z, acc);
                acc = fmaf(w.w, p.w, acc);
            }
            d_Ep[(lane * 33 + 32) * Cn + c] = acc;
        } else {
            const int ks = blk0 - 1312;   // 0..16
            spin_ge(&g_cB, 32);
            if (ks != 8) {
                const int kc = (ks < 8) ? ks : (ks - 9);
                for (int i = t; i < 32 * 32; i += 256) {
                    int bb = i >> 5, kk = i & 31;
                    sm.c.h[bb * 33 + kk] = d_h[bb * HIDn + kc * 32 + kk];
                }
            }
            if (ks <= 8) {
                for (int i = t; i < 32 * 64; i += 256) {
                    int bb = i >> 6, r = i & 63;
                    sm.c.phi[bb * 68 + r] = d_phis[bb * RANKn + r];
                }
            }
            __syncthreads();

            const int j = warp;
            if (ks < 8) {
                float acc = 0.f;
                const float* Wbase = W_Ws + (size_t)(ks * 32) * (OSn * RANKn) + j * RANKn;
                #pragma unroll 2
                for (int kk = 0; kk < 32; kk++) {
                    float hk = sm.c.h[lane * 33 + kk];
                    const float4* w4 = (const float4*)(Wbase + (size_t)kk * (OSn * RANKn));
                    float dot = 0.f;
                    #pragma unroll
                    for (int r4 = 0; r4 < 16; r4++) {
                        float4 w = __ldg(&w4[r4]);
                        float4 p = *(const float4*)(sm.c.phi + lane * 68 + r4 * 4);
                        dot = fmaf(w.x, p.x, dot);
                        dot = fmaf(w.y, p.y, dot);
                        dot = fmaf(w.z, p.z, dot);
                        dot = fmaf(w.w, p.w, dot);
                    }
                    acc = fmaf(hk, dot, acc);
                }
                d_Sp[(lane * 9 + ks) * OSn + j] = acc;
            } else if (ks == 8) {
                float acc = 0.f;
                const float4* bw4 = (const float4*)(b_Ws + j * RANKn);
                #pragma unroll
                for (int r4 = 0; r4 < 16; r4++) {
                    float4 w = __ldg(&bw4[r4]);
                    float4 p = *(const float4*)(sm.c.phi + lane * 68 + r4 * 4);
                    acc = fmaf(w.x, p.x, acc);
                    acc = fmaf(w.y, p.y, acc);
                    acc = fmaf(w.z, p.z, acc);
                    acc = fmaf(w.w, p.w, acc);
                }
                d_Sp[(lane * 9 + 8) * OSn + j] = acc;
            } else {
                const int kc = ks - 9;
                float a0 = 0.f;
                const float* Wb = W_bs + (size_t)(kc * 32) * OSn + j;
                #pragma unroll 4
                for (int kk = 0; kk < 32; kk++)
                    a0 = fmaf(sm.c.h[lane * 33 + kk], __ldg(Wb + (size_t)kk * OSn), a0);
                d_MBp[(lane * 8 + kc) * OSn + j] = a0;
            }
        }
        __threadfence();
        __syncthreads();
        if (t == 0) atomicAdd(&g_cC, 1);
    } else {
        // ================= stage F: tables + stencil + output stream =================
        const int q   = blk - B0_F;
        const int hwt = q & 3;
        const int bcg = q >> 2;
        const int b   = bcg >> 3;
        const int cg  = bcg & 7;
        const int hw4 = hwt * 256 + t;

        const size_t base = ((size_t)(b * Cn + cg * 32)) * (HWn / 4) + hw4;
        const float4* x4 = (const float4*)x;

        // prefetch first 8 channels of x into smem BEFORE the gate
        #pragma unroll
        for (int ci = 0; ci < 8; ci++)
            sm.xbuf[ci * 256 + t] = __ldg(&x4[base + (size_t)ci * (HWn / 4)]);

        spin_ge(&g_cC, NB_C);

        if (t < 32) {
            const int c = cg * 32 + t;
            float e = 0.f;
            #pragma unroll
            for (int ks = 0; ks < 33; ks++) e += d_Ep[(b * 33 + ks) * Cn + c];
            float m = __ldg(b_bc + c);
            #pragma unroll
            for (int kc = 0; kc < 8; kc++) m += d_Mp[(b * 8 + kc) * Cn + c];
            float cm = m * e;
            sig_s[t] = 1.f / (1.f + expf(-cm));
        } else if (t < 40) {
            const int j = t - 32;
            float e = 0.f;
            #pragma unroll
            for (int ks = 0; ks < 9; ks++) e += d_Sp[(b * 9 + ks) * OSn + j];
            float m = __ldg(b_bs + j);
            #pragma unroll
            for (int kc = 0; kc < 8; kc++) m += d_MBp[(b * 8 + kc) * OSn + j];
            sms_s[j] = m * e;
        }
        __syncthreads();

        if (t < 8) {
            pc_s[(t >> 2) * 5 + (t & 3)] = sms_s[t];
        } else if (t < 10) {
            int jj = t - 8;
            pc_s[jj * 5 + 4] = -(sms_s[jj * 4] + sms_s[jj * 4 + 1] + sms_s[jj * 4 + 2] + sms_s[jj * 4 + 3]);
        }
        __syncthreads();

        const float* a0p = d_av0 + b * HWn;
        const float* a1p = d_av1 + b * HWn;
        const float* m0p = d_mx0 + b * HWn;
        const float* m1p = d_mx1 + b * HWn;
        const float cs = 1.f / (float)Cn;

        float cvr[4];
        #pragma unroll
        for (int j = 0; j < 4; j++) {
            const int p  = hw4 * 4 + j;
            const int hh = p >> 6, ww = p & 63;
            float up_a = (hh > 0)      ? (__ldg(a0p + p - Wn) + __ldg(a1p + p - Wn)) * cs : 0.f;
            float dn_a = (hh < Hn - 1) ? (__ldg(a0p + p + Wn) + __ldg(a1p + p + Wn)) * cs : 0.f;
            float lf_a = (ww > 0)      ? (__ldg(a0p + p - 1)  + __ldg(a1p + p - 1))  * cs : 0.f;
            float rt_a = (ww < Wn - 1) ? (__ldg(a0p + p + 1)  + __ldg(a1p + p + 1))  * cs : 0.f;
            float ce_a = (__ldg(a0p + p) + __ldg(a1p + p)) * cs;
            float up_m = (hh > 0)      ? fmaxf(__ldg(m0p + p - Wn), __ldg(m1p + p - Wn)) : 0.f;
            float dn_m = (hh < Hn - 1) ? fmaxf(__ldg(m0p + p + Wn), __ldg(m1p + p + Wn)) : 0.f;
            float lf_m = (ww > 0)      ? fmaxf(__ldg(m0p + p - 1),  __ldg(m1p + p - 1))  : 0.f;
            float rt_m = (ww < Wn - 1) ? fmaxf(__ldg(m0p + p + 1),  __ldg(m1p + p + 1))  : 0.f;
            float ce_m = fmaxf(__ldg(m0p + p), __ldg(m1p + p));

            float conv = pc_s[0] * up_a + pc_s[1] * dn_a + pc_s[2] * lf_a + pc_s[3] * rt_a + pc_s[4] * ce_a
                       + pc_s[5] * up_m + pc_s[6] * dn_m + pc_s[7] * lf_m + pc_s[8] * rt_m + pc_s[9] * ce_m;
            cvr[j] = 1.f / (1.f + expf(-conv));
        }

        float4* o4 = (float4*)out;

        #pragma unroll
        for (int ci = 0; ci < 8; ci++) {
            float s = sig_s[ci] + 1.f;
            float4 v = sm.xbuf[ci * 256 + t];
            float4 o;
            o.x = v.x * (s + cvr[0]);
            o.y = v.y * (s + cvr[1]);
            o.z = v.z * (s + cvr[2]);
            o.w = v.w * (s + cvr[3]);
            o4[base + (size_t)ci * (HWn / 4)] = o;
        }
        #pragma unroll 8
        for (int ci = 8; ci < 32; ci++) {
            float s = sig_s[ci] + 1.f;
            float4 v = __ldg(&x4[base + (size_t)ci * (HWn / 4)]);
            float4 o;
            o.x = v.x * (s + cvr[0]);
            o.y = v.y * (s + cvr[1]);
            o.z = v.z * (s + cvr[2]);
            o.w = v.w * (s + cvr[3]);
            o4[base + (size_t)ci * (HWn / 4)] = o;
        }

        __syncthreads();
        if (t == 0) {
            int old = atomicAdd(&g_cF, 1);
            if (old == NB_F - 1) {
                #pragma unroll
                for (int i = 0; i < Bn; i++) { g_cK[i] = 0; g_cA[i] = 0; }
                g_cB = 0; g_cC = 0; g_cF = 0;
            }
        }
    }
}

// ---------------- launch ----------------
extern "C" void kernel_launch(void* const* d_in, const int* in_sizes, int n_in,
                              void* d_out, int out_size) {
    (void)in_sizes; (void)n_in; (void)out_size;
    const float* x     = (const float*)d_in[0];
    const float* a     = (const float*)d_in[1];
    const float* W_pre = (const float*)d_in[2];
    const float* b_pre = (const float*)d_in[3];
    const float* W_bc  = (const float*)d_in[4];
    const float* b_bc  = (const float*)d_in[5];
    const float* W_bs  = (const float*)d_in[6];
    const float* b_bs  = (const float*)d_in[7];
    const float* W_pc  = (const float*)d_in[8];
    const float* b_pc  = (const float*)d_in[9];
    const float* W_ps  = (const float*)d_in[10];
    const float* b_ps  = (const float*)d_in[11];
    const float* W_Wc  = (const float*)d_in[12];
    const float* b_Wc  = (const float*)d_in[13];
    const float* W_Ws  = (const float*)d_in[14];
    const float* b_Ws  = (const float*)d_in[15];
    float* out = (float*)d_out;

    mega<<<NB_TOT, 256>>>(x, out, a,
                          W_pre, b_pre, W_pc, b_pc, W_ps, b_ps,
                          W_Wc, b_Wc, W_bc, b_bc, W_Ws, b_Ws, W_bs, b_bs);
}

// round 13
// speedup vs baseline: 1.1622x; 1.1622x over previous
#include <cuda_runtime.h>
#include <math.h>

#define Bn   32
#define Cn   256
#define Hn   64
#define Wn   64
#define HWn  4096
#define AUXn 64
#define RANKn 64
#define HIDn 256
#define OSn  8
#define PI_F 3.14159265358979323846f

// ---------------- scratch ----------------
__device__ __align__(128) float d_gpart[Bn * 16 * Cn];
__device__ __align__(128) float d_av0[Bn * HWn];
__device__ __align__(128) float d_av1[Bn * HWn];
__device__ __align__(128) float d_mx0[Bn * HWn];
__device__ __align__(128) float d_mx1[Bn * HWn];
__device__ __align__(128) float d_h[Bn * HIDn];
__device__ __align__(128) float d_phic[Bn * RANKn];
__device__ __align__(128) float d_phis[Bn * RANKn];
__device__ __align__(128) float d_Ep[Bn * 33 * Cn];
__device__ __align__(128) float d_Mp[Bn * 8 * Cn];
__device__ __align__(128) float d_Sp[Bn * 9 * OSn];
__device__ __align__(128) float d_MBp[Bn * 8 * OSn];

// dependency counters (reset by last stage-C block each run)
__device__ int g_cA[Bn];
__device__ int g_cB;
__device__ int g_cC;

__device__ __forceinline__ void spin_ge(int* ctr, int target) {
    if (threadIdx.x == 0) {
        while (atomicAdd(ctr, 0) < target) __nanosleep(64);
    }
    __syncthreads();
}

// ---------------- K1: stats pass (measured 33.3us @ 52% DRAM) ----------------
__global__ void k1_stats(const float* __restrict__ x) {
    const int tile  = blockIdx.x;
    const int b     = blockIdx.y;
    const int chalf = blockIdx.z;
    const int t     = threadIdx.x;
    const int warp  = t >> 5, lane = t & 31;
    const int pos0  = tile * 256;

    __shared__ float rs[128 * 33];
    __shared__ float avp[8][256];
    __shared__ float mxp[8][256];

    const float4* xb = (const float4*)(x + (size_t)b * Cn * HWn);
    const int p4base = (pos0 >> 2) + lane;

    float4 av0 = {0,0,0,0}, av1 = {0,0,0,0};
    const float NI = -3.402823466e38f;
    float4 mx0 = {NI,NI,NI,NI}, mx1 = mx0;

    const int lcbase = warp * 16;
    const int cbase  = chalf * 128 + lcbase;
    #pragma unroll 4
    for (int cc = 0; cc < 16; cc++) {
        const size_t row = (size_t)(cbase + cc) * (HWn / 4) + p4base;
        float4 v0 = __ldg(&xb[row]);
        float4 v1 = __ldg(&xb[row + 32]);

        av0.x += v0.x; av0.y += v0.y; av0.z += v0.z; av0.w += v0.w;
        av1.x += v1.x; av1.y += v1.y; av1.z += v1.z; av1.w += v1.w;
        mx0.x = fmaxf(mx0.x, v0.x); mx0.y = fmaxf(mx0.y, v0.y); mx0.z = fmaxf(mx0.z, v0.z); mx0.w = fmaxf(mx0.w, v0.w);
        mx1.x = fmaxf(mx1.x, v1.x); mx1.y = fmaxf(mx1.y, v1.y); mx1.z = fmaxf(mx1.z, v1.z); mx1.w = fmaxf(mx1.w, v1.w);

        float r = ((v0.x + v0.y) + (v0.z + v0.w)) + ((v1.x + v1.y) + (v1.z + v1.w));
        rs[(lcbase + cc) * 33 + lane] = r;
    }

    *(float4*)&avp[warp][lane * 4]       = av0;
    *(float4*)&avp[warp][128 + lane * 4] = av1;
    *(float4*)&mxp[warp][lane * 4]       = mx0;
    *(float4*)&mxp[warp][128 + lane * 4] = mx1;
    __syncthreads();

    {
        float s = 0.f, m = NI;
        #pragma unroll
        for (int w = 0; w < 8; w++) { s += avp[w][t]; m = fmaxf(m, mxp[w][t]); }
        float* avh = chalf ? d_av1 : d_av0;
        float* mxh = chalf ? d_mx1 : d_mx0;
        avh[b * HWn + pos0 + t] = s;
        mxh[b * HWn + pos0 + t] = m;
    }
    if (t < 128) {
        float g = 0.f;
        #pragma unroll
        for (int l = 0; l < 32; l++) g += rs[t * 33 + l];
        d_gpart[(b * 16 + tile) * Cn + chalf * 128 + t] = g;
    }
}

// ---------------- K23: staged mega-kernel (A: h, B: phi, C: contractions) ----------------
// blocks [0,256):    stage A — h partials: b = blk>>3, part = blk&7
// blocks [256,288):  stage B — phi for b = blk-256 (per-batch gate on g_cA[b]==8)
// blocks [288,1105): stage C — contractions (gate g_cB==32; GEMM W tile prefetched BEFORE gate)
__global__ void __launch_bounds__(256) k23(
        const float* __restrict__ a,
        const float* __restrict__ W_pre, const float* __restrict__ b_pre,
        const float* __restrict__ W_pc,  const float* __restrict__ b_pc,
        const float* __restrict__ W_ps,  const float* __restrict__ b_ps,
        const float* __restrict__ W_Wc,  const float* __restrict__ b_Wc,
        const float* __restrict__ W_bc,
        const float* __restrict__ W_Ws,  const float* __restrict__ b_Ws,
        const float* __restrict__ W_bs) {
    const int blk = blockIdx.x;
    const int t   = threadIdx.x;
    const int lane = t & 31;
    const int warp = t >> 5;

    __shared__ float S_Wt[8 * 1024];     // 32 KB (stage C GEMM tile)
    __shared__ float S_h[32 * 33];
    __shared__ float S_phi[32 * 68];

    if (blk < 256) {
        // ================= stage A: partial h =================
        const int b = blk >> 3, part = blk & 7;
        float* in_s = S_h;
        float* red  = S_phi;

        {
            float g = 0.f;
            #pragma unroll
            for (int tl = 0; tl < 16; tl++) g += d_gpart[(b * 16 + tl) * Cn + t];
            in_s[t] = g * (1.f / (float)HWn);
            if (t < AUXn) in_s[Cn + t] = __ldg(a + b * AUXn + t);
        }
        __syncthreads();

        const int j  = t & 31;
        const int ks = t >> 5;
        const int jg = part * 32 + j;
        float acc = (ks == 0) ? __ldg(b_pre + jg) : 0.f;
        const int i0 = ks * 40;
        #pragma unroll
        for (int k = 0; k < 40; k++)
            acc = fmaf(in_s[i0 + k], __ldg(W_pre + (i0 + k) * HIDn + jg), acc);
        red[ks * 32 + j] = acc;
        __syncthreads();

        if (t < 32) {
            float s = 0.f;
            #pragma unroll
            for (int kk = 0; kk < 8; kk++) s += red[kk * 32 + t];
            d_h[b * HIDn + part * 32 + t] = fmaxf(s, 0.f);
        }
        __threadfence();
        __syncthreads();
        if (t == 0) atomicAdd(&g_cA[b], 1);
    } else if (blk < 288) {
        // ================= stage B: phi (per-batch gate) =================
        const int b = blk - 256;
        spin_ge(&g_cA[b], 8);

        float* h_s   = S_h;
        float* pcred = S_phi;
        float* psred = S_phi + 256;
        h_s[t] = d_h[b * HIDn + t];
        __syncthreads();

        const int j  = t & 31;
        const int ks = t >> 5;
        {
            float pc = (ks == 0) ? __ldg(b_pc + j) : 0.f;
            float ps = (ks == 0) ? __ldg(b_ps + j) : 0.f;
            const int k0 = ks * 32;
            #pragma unroll 4
            for (int k = 0; k < 32; k++) {
                float hk = h_s[k0 + k];
                pc = fmaf(hk, __ldg(W_pc + (k0 + k) * RANKn + j), pc);
                ps = fmaf(hk, __ldg(W_ps + (k0 + k) * RANKn + j), ps);
            }
            pcred[ks * 32 + j] = pc;
            psred[ks * 32 + j] = ps;
        }
        __syncthreads();

        if (t < 32) {
            float p = 0.f;
            #pragma unroll
            for (int kk = 0; kk < 8; kk++) p += pcred[kk * 32 + t];
            float w = 1.f + (PI_F - 1.f) * (float)t / 31.f;
            float u = p * w;
            d_phic[b * RANKn + t]      = sinf(u);
            d_phic[b * RANKn + t + 32] = cosf(u);
        } else if (t < 64) {
            int r = t - 32;
            float p = 0.f;
            #pragma unroll
            for (int kk = 0; kk < 8; kk++) p += psred[kk * 32 + r];
            float w = 1.f + (PI_F - 1.f) * (float)r / 31.f;
            float u = p * w;
            d_phis[b * RANKn + r]      = sinf(u);
            d_phis[b * RANKn + r + 32] = cosf(u);
        }
        __threadfence();
        __syncthreads();
        if (t == 0) atomicAdd(&g_cB, 1);
    } else {
        // ================= stage C: contractions =================
        const int blk0 = blk - 288;
        float* Wt    = S_Wt;
        float* h_s   = S_h;
        float* phi_s = S_phi;

        if (blk0 < 512) {
            const int kt = blk0 >> 4;
            const int ct = blk0 & 15;

            // ---- prefetch W tile BEFORE the gate (W independent of A/B) ----
            const float4* Wg = (const float4*)(W_Wc + (size_t)(kt * 8) * (Cn * RANKn) + ct * 1024);
            #pragma unroll
            for (int i = t; i < 2048; i += 256) {
                int kk = i >> 8, jj = i & 255;
                ((float4*)Wt)[i] = __ldg(&Wg[(size_t)kk * 4096 + jj]);
            }

            spin_ge(&g_cB, 32);

            {
                int bb = t >> 3, kk = t & 7;
                h_s[bb * 33 + kk] = d_h[bb * HIDn + kt * 8 + kk];
            }
            for (int i = t; i < 2048; i += 256) {
                int bb = i >> 6, r = i & 63;
                phi_s[bb * 68 + r] = d_phic[bb * RANKn + r];
            }
            __syncthreads();

            float4 ph[16];
            #pragma unroll
            for (int i = 0; i < 16; i++) ph[i] = *(const float4*)(phi_s + lane * 68 + i * 4);

            #pragma unroll
            for (int cj = 0; cj < 2; cj++) {
                const int cl = warp * 2 + cj;
                float acc = 0.f;
                #pragma unroll
                for (int kk = 0; kk < 8; kk++) {
                    const float4* w4 = (const float4*)(Wt + kk * 1024 + cl * 64);
                    float d0 = 0.f, d1 = 0.f;
                    #pragma unroll
                    for (int q = 0; q < 16; q += 2) {
                        float4 wa = w4[q], wb = w4[q + 1];
                        d0 = fmaf(wa.x, ph[q].x, d0);
                        d0 = fmaf(wa.y, ph[q].y, d0);
                        d0 = fmaf(wa.z, ph[q].z, d0);
                        d0 = fmaf(wa.w, ph[q].w, d0);
                        d1 = fmaf(wb.x, ph[q + 1].x, d1);
                        d1 = fmaf(wb.y, ph[q + 1].y, d1);
                        d1 = fmaf(wb.z, ph[q + 1].z, d1);
                        d1 = fmaf(wb.w, ph[q + 1].w, d1);
                    }
                    acc = fmaf(h_s[lane * 33 + kk], d0 + d1, acc);
                }
                d_Ep[(lane * 33 + kt) * Cn + ct * 16 + cl] = acc;
            }
        } else if (blk0 < 768) {
            const int q = blk0 - 512;
            const int ct8 = q & 31, kc = q >> 5;
            const int c = ct8 * 8 + warp;
            spin_ge(&g_cB, 32);
            for (int i = t; i < 32 * 32; i += 256) {
                int bb = i >> 5, kk = i & 31;
                h_s[bb * 33 + kk] = d_h[bb * HIDn + kc * 32 + kk];
            }
            __syncthreads();
            float a0 = 0.f, a1 = 0.f;
            const float* Wb = W_bc + (size_t)(kc * 32) * Cn + c;
            #pragma unroll 4
            for (int kk = 0; kk < 32; kk += 2) {
                a0 = fmaf(h_s[lane * 33 + kk],     __ldg(Wb + (size_t)kk * Cn), a0);
                a1 = fmaf(h_s[lane * 33 + kk + 1], __ldg(Wb + (size_t)(kk + 1) * Cn), a1);
            }
            d_Mp[(lane * 8 + kc) * Cn + c] = a0 + a1;
        } else if (blk0 < 800) {
            const int ct8 = blk0 - 768;
            const int c = ct8 * 8 + warp;
            spin_ge(&g_cB, 32);
            for (int i = t; i < 32 * 64; i += 256) {
                int bb = i >> 6, r = i & 63;
                phi_s[bb * 68 + r] = d_phic[bb * RANKn + r];
            }
            __syncthreads();
            float acc = 0.f;
            const float4* bw4 = (const float4*)(b_Wc + c * RANKn);
            #pragma unroll
            for (int r4 = 0; r4 < 16; r4++) {
                float4 w = __ldg(&bw4[r4]);
                float4 p = *(const float4*)(phi_s + lane * 68 + r4 * 4);
                acc = fmaf(w.x, p.x, acc);
                acc = fmaf(w.y, p.y, acc);
                acc = fmaf(w.z, p.z, acc);
                acc = fmaf(w.w, p.w, acc);
            }
            d_Ep[(lane * 33 + 32) * Cn + c] = acc;
        } else {
            const int ks = blk0 - 800;   // 0..16
            spin_ge(&g_cB, 32);
            if (ks != 8) {
                const int kc = (ks < 8) ? ks : (ks - 9);
                for (int i = t; i < 32 * 32; i += 256) {
                    int bb = i >> 5, kk = i & 31;
                    h_s[bb * 33 + kk] = d_h[bb * HIDn + kc * 32 + kk];
                }
            }
            if (ks <= 8) {
                for (int i = t; i < 32 * 64; i += 256) {
                    int bb = i >> 6, r = i & 63;
                    phi_s[bb * 68 + r] = d_phis[bb * RANKn + r];
                }
            }
            __syncthreads();

            const int j = warp;
            if (ks < 8) {
                float acc = 0.f;
                const float* Wbase = W_Ws + (size_t)(ks * 32) * (OSn * RANKn) + j * RANKn;
                #pragma unroll 2
                for (int kk = 0; kk < 32; kk++) {
                    float hk = h_s[lane * 33 + kk];
                    const float4* w4 = (const float4*)(Wbase + (size_t)kk * (OSn * RANKn));
                    float dot = 0.f;
                    #pragma unroll
                    for (int r4 = 0; r4 < 16; r4++) {
                        float4 w = __ldg(&w4[r4]);
                        float4 p = *(const float4*)(phi_s + lane * 68 + r4 * 4);
                        dot = fmaf(w.x, p.x, dot);
                        dot = fmaf(w.y, p.y, dot);
                        dot = fmaf(w.z, p.z, dot);
                        dot = fmaf(w.w, p.w, dot);
                    }
                    acc = fmaf(hk, dot, acc);
                }
                d_Sp[(lane * 9 + ks) * OSn + j] = acc;
            } else if (ks == 8) {
                float acc = 0.f;
                const float4* bw4 = (const float4*)(b_Ws + j * RANKn);
                #pragma unroll
                for (int r4 = 0; r4 < 16; r4++) {
                    float4 w = __ldg(&bw4[r4]);
                    float4 p = *(const float4*)(phi_s + lane * 68 + r4 * 4);
                    acc = fmaf(w.x, p.x, acc);
                    acc = fmaf(w.y, p.y, acc);
                    acc = fmaf(w.z, p.z, acc);
                    acc = fmaf(w.w, p.w, acc);
                }
                d_Sp[(lane * 9 + 8) * OSn + j] = acc;
            } else {
                const int kc = ks - 9;
                float a0 = 0.f;
                const float* Wb = W_bs + (size_t)(kc * 32) * OSn + j;
                #pragma unroll 4
                for (int kk = 0; kk < 32; kk++)
                    a0 = fmaf(h_s[lane * 33 + kk], __ldg(Wb + (size_t)kk * OSn), a0);
                d_MBp[(lane * 8 + kc) * OSn + j] = a0;
            }
        }
        // completion + counter reset for next graph replay
        __syncthreads();
        if (t == 0) {
            int old = atomicAdd(&g_cC, 1);
            if (old == 816) {
                #pragma unroll
                for (int i = 0; i < Bn; i++) g_cA[i] = 0;
                g_cB = 0; g_cC = 0;
            }
        }
    }
}

// ---------------- K5: fused tables + stencil + output stream (measured ~47us) ----------------
__global__ void k5_out(const float* __restrict__ x, float* __restrict__ out,
                       const float* __restrict__ b_bc, const float* __restrict__ b_bs) {
    const int t   = threadIdx.x;
    const int hw4 = blockIdx.x * 256 + t;
    const int bcg = blockIdx.y;
    const int b   = bcg >> 3;
    const int cg  = bcg & 7;

    __shared__ float sig_s[32];
    __shared__ float sm_s[OSn];
    __shared__ float pc_s[10];

    if (t < 32) {
        const int c = cg * 32 + t;
        float e = 0.f;
        #pragma unroll
        for (int ks = 0; ks < 33; ks++) e += d_Ep[(b * 33 + ks) * Cn + c];
        float m = __ldg(b_bc + c);
        #pragma unroll
        for (int kc = 0; kc < 8; kc++) m += d_Mp[(b * 8 + kc) * Cn + c];
        float cm = m * e;
        sig_s[t] = 1.f / (1.f + expf(-cm));
    } else if (t < 40) {
        const int j = t - 32;
        float e = 0.f;
        #pragma unroll
        for (int ks = 0; ks < 9; ks++) e += d_Sp[(b * 9 + ks) * OSn + j];
        float m = __ldg(b_bs + j);
        #pragma unroll
        for (int kc = 0; kc < 8; kc++) m += d_MBp[(b * 8 + kc) * OSn + j];
        sm_s[j] = m * e;
    }
    __syncthreads();

    if (t < 8) {
        pc_s[(t >> 2) * 5 + (t & 3)] = sm_s[t];
    } else if (t < 10) {
        int jj = t - 8;
        pc_s[jj * 5 + 4] = -(sm_s[jj * 4] + sm_s[jj * 4 + 1] + sm_s[jj * 4 + 2] + sm_s[jj * 4 + 3]);
    }
    __syncthreads();

    const float* a0 = d_av0 + b * HWn;
    const float* a1 = d_av1 + b * HWn;
    const float* m0 = d_mx0 + b * HWn;
    const float* m1 = d_mx1 + b * HWn;
    const float cs = 1.f / (float)Cn;

    float cvr[4];
    #pragma unroll
    for (int j = 0; j < 4; j++) {
        const int p  = hw4 * 4 + j;
        const int hh = p >> 6, ww = p & 63;
        float up_a = (hh > 0)      ? (__ldg(a0 + p - Wn) + __ldg(a1 + p - Wn)) * cs : 0.f;
        float dn_a = (hh < Hn - 1) ? (__ldg(a0 + p + Wn) + __ldg(a1 + p + Wn)) * cs : 0.f;
        float lf_a = (ww > 0)      ? (__ldg(a0 + p - 1)  + __ldg(a1 + p - 1))  * cs : 0.f;
        float rt_a = (ww < Wn - 1) ? (__ldg(a0 + p + 1)  + __ldg(a1 + p + 1))  * cs : 0.f;
        float ce_a = (__ldg(a0 + p) + __ldg(a1 + p)) * cs;
        float up_m = (hh > 0)      ? fmaxf(__ldg(m0 + p - Wn), __ldg(m1 + p - Wn)) : 0.f;
        float dn_m = (hh < Hn - 1) ? fmaxf(__ldg(m0 + p + Wn), __ldg(m1 + p + Wn)) : 0.f;
        float lf_m = (ww > 0)      ? fmaxf(__ldg(m0 + p - 1),  __ldg(m1 + p - 1))  : 0.f;
        float rt_m = (ww < Wn - 1) ? fmaxf(__ldg(m0 + p + 1),  __ldg(m1 + p + 1))  : 0.f;
        float ce_m = fmaxf(__ldg(m0 + p), __ldg(m1 + p));

        float conv = pc_s[0] * up_a + pc_s[1] * dn_a + pc_s[2] * lf_a + pc_s[3] * rt_a + pc_s[4] * ce_a
                   + pc_s[5] * up_m + pc_s[6] * dn_m + pc_s[7] * lf_m + pc_s[8] * rt_m + pc_s[9] * ce_m;
        cvr[j] = 1.f / (1.f + expf(-conv));
    }

    const size_t base = ((size_t)(b * Cn + cg * 32)) * (HWn / 4) + hw4;
    const float4* x4 = (const float4*)x;
    float4* o4 = (float4*)out;

    #pragma unroll 8
    for (int ci = 0; ci < 32; ci++) {
        float s = sig_s[ci] + 1.f;
        float4 v = __ldg(&x4[base + (size_t)ci * (HWn / 4)]);
        float4 o;
        o.x = v.x * (s + cvr[0]);
        o.y = v.y * (s + cvr[1]);
        o.z = v.z * (s + cvr[2]);
        o.w = v.w * (s + cvr[3]);
        o4[base + (size_t)ci * (HWn / 4)] = o;
    }
}

// ---------------- launch ----------------
extern "C" void kernel_launch(void* const* d_in, const int* in_sizes, int n_in,
                              void* d_out, int out_size) {
    (void)in_sizes; (void)n_in; (void)out_size;
    const float* x     = (const float*)d_in[0];
    const float* a     = (const float*)d_in[1];
    const float* W_pre = (const float*)d_in[2];
    const float* b_pre = (const float*)d_in[3];
    const float* W_bc  = (const float*)d_in[4];
    const float* b_bc  = (const float*)d_in[5];
    const float* W_bs  = (const float*)d_in[6];
    const float* b_bs  = (const float*)d_in[7];
    const float* W_pc  = (const float*)d_in[8];
    const float* b_pc  = (const float*)d_in[9];
    const float* W_ps  = (const float*)d_in[10];
    const float* b_ps  = (const float*)d_in[11];
    const float* W_Wc  = (const float*)d_in[12];
    const float* b_Wc  = (const float*)d_in[13];
    const float* W_Ws  = (const float*)d_in[14];
    const float* b_Ws  = (const float*)d_in[15];
    float* out = (float*)d_out;

    k1_stats<<<dim3(16, Bn, 2), 256>>>(x);                              // launch 0
    k23<<<1105, 256>>>(a, W_pre, b_pre, W_pc, b_pc, W_ps, b_ps,
                       W_Wc, b_Wc, W_bc, W_Ws, b_Ws, W_bs);             // launch 1
    k5_out<<<dim3(4, Bn * 8), 256>>>(x, out, b_bc, b_bs);               // launch 2
}